// round 10
// baseline (speedup 1.0000x reference)
#include <cuda_runtime.h>
#include <cuda_bf16.h>

#define H      2048
#define E      64
#define NTOK   16384
#define TM     128
#define NBLK   128
#define NPAIR  16

typedef unsigned int u32;

// -------- device scratch (allocation-free) --------
__device__ __align__(16) unsigned char g_Wh[32 * 8192];
__device__ __align__(16) unsigned char g_Wm[32 * 8192];
__device__ float g_part_load[NBLK * E];
__device__ float g_part_z[NBLK];
__device__ unsigned int g_arrive = 0;

#define SWZ(o) ((o) ^ (((o) >> 3) & 0x70))
#define GAP_TH 4e-4f

// 4 tile-slots of 48KB: Ah(16K) Am(16K) Bh(8K) Bm(8K)
#define SLOT_SZ 49152
#define SLOT(par, t) (((par) * 2 + (t)) * SLOT_SZ)
#define A_H 0
#define A_M 16384
#define B_H 32768
#define B_M 40960
#define SMEM_DYN (4 * SLOT_SZ)

__device__ __forceinline__ u32 smem_u32(const void* p) {
    u32 a;
    asm("{ .reg .u64 t; cvta.to.shared.u64 t, %1; cvt.u32.u64 %0, t; }" : "=r"(a) : "l"(p));
    return a;
}

#define CP16(dst, src) \
    asm volatile("cp.async.cg.shared.global [%0], [%1], 16;" :: "r"(dst), "l"(src) : "memory")
#define CP_COMMIT() asm volatile("cp.async.commit_group;" ::: "memory")
#define CP_WAIT0()  asm volatile("cp.async.wait_group 0;" ::: "memory")
#define CP_WAIT1()  asm volatile("cp.async.wait_group 1;" ::: "memory")

#define LDSM4(r0, r1, r2, r3, addr) \
    asm volatile("ldmatrix.sync.aligned.m8n8.x4.shared.b16 {%0,%1,%2,%3}, [%4];" \
        : "=r"(r0), "=r"(r1), "=r"(r2), "=r"(r3) : "r"(addr))

#define MMA(d, a, b0, b1) \
    asm volatile("mma.sync.aligned.m16n8k16.row.col.f32.bf16.bf16.f32 " \
        "{%0,%1,%2,%3}, {%4,%5,%6,%7}, {%8,%9}, {%0,%1,%2,%3};" \
        : "+f"((d)[0]), "+f"((d)[1]), "+f"((d)[2]), "+f"((d)[3]) \
        : "r"((a)[0]), "r"((a)[1]), "r"((a)[2]), "r"((a)[3]), "r"(b0), "r"(b1))

// 2-limb bf16 split of a float pair (residual exact in fp32)
__device__ __forceinline__ void split2(float a, float b, u32& h, u32& m) {
    __nv_bfloat162 hb = __floats2bfloat162_rn(a, b);
    float2 hf = __bfloat1622float2(hb);
    __nv_bfloat162 mb = __floats2bfloat162_rn(a - hf.x, b - hf.y);
    h = *(u32*)&hb; m = *(u32*)&mb;
}

// -------- prep: split + pre-swizzle W --------
__global__ __launch_bounds__(256) void prep_kernel(const float* __restrict__ W) {
    int e = blockIdx.x;
    int t = threadIdx.x;
    int k0 = t * 8;
    int kt = k0 >> 6;
    int c  = k0 & 63;
    const float4* src = (const float4*)(W + (size_t)e * H + k0);
    float4 a = src[0], b = src[1];
    uint4 Hv, Mv;
    split2(a.x, a.y, Hv.x, Mv.x);
    split2(a.z, a.w, Hv.y, Mv.y);
    split2(b.x, b.y, Hv.z, Mv.z);
    split2(b.z, b.w, Hv.w, Mv.w);
    u32 off = kt * 8192 + SWZ((u32)(e * 128 + c * 2));
    *(uint4*)(g_Wh + off) = Hv;
    *(uint4*)(g_Wm + off) = Mv;
}

__device__ __forceinline__ void pass8(float (*acc)[4], const u32* a, const u32* b) {
    #pragma unroll
    for (int g = 0; g < 4; g++) {
        MMA(acc[2*g],   a, b[4*g],   b[4*g+1]);
        MMA(acc[2*g+1], a, b[4*g+2], b[4*g+3]);
    }
}
__device__ __forceinline__ void ldsm_grp(u32* b, u32 base, int c, int rowpart, int kb16) {
    #pragma unroll
    for (int g = 0; g < 4; g++) {
        u32 off = (u32)((g * 16 + rowpart) * 128 + c * 32 + kb16);
        LDSM4(b[4*g], b[4*g+1], b[4*g+2], b[4*g+3], base + SWZ(off));
    }
}

// per-tile compute: A via ldmatrix, 3 products (hh, mh, hm)
__device__ __forceinline__ void compute_tile(u32 slot, float (*acc)[4], int wl, int lane)
{
    const int arow = ((lane >> 3) & 1) * 8 + (lane & 7);
    const int acol = (lane >> 4) * 8;
    const int rowpart = ((lane >> 4) & 1) * 8 + (lane & 7);
    const int kb16 = ((lane >> 3) & 1) * 16;
    u32 bh[16], bm[16];
    ldsm_grp(bh, slot + B_H, 0, rowpart, kb16);
    #pragma unroll
    for (int c = 0; c < 4; c++) {
        u32 ah[4], am[4];
        u32 aoff = SWZ((u32)((wl * 16 + arow) * 128 + (c * 16 + acol) * 2));
        LDSM4(ah[0], ah[1], ah[2], ah[3], slot + A_H + aoff);
        LDSM4(am[0], am[1], am[2], am[3], slot + A_M + aoff);
        ldsm_grp(bm, slot + B_M, c, rowpart, kb16);
        pass8(acc, ah, bh);
        pass8(acc, am, bh);
        if (c < 3) ldsm_grp(bh, slot + B_H, c + 1, rowpart, kb16);
        pass8(acc, ah, bm);
    }
}

// convert 32 fp32 x values -> 2 swizzled bf16 A tiles
__device__ __forceinline__ void convert_store(
    const float4* xr, unsigned char* slotp, int row, int half32)
{
    #pragma unroll
    for (int q = 0; q < 4; q++) {
        float4 v0 = xr[2*q], v1 = xr[2*q+1];
        uint4 Hv, Mv;
        split2(v0.x, v0.y, Hv.x, Mv.x);
        split2(v0.z, v0.w, Hv.y, Mv.y);
        split2(v1.x, v1.y, Hv.z, Mv.z);
        split2(v1.z, v1.w, Hv.w, Mv.w);
        u32 sw = SWZ((u32)(row * 128 + half32 * 64 + q * 16));
        *(uint4*)(slotp + A_H + sw) = Hv;
        *(uint4*)(slotp + A_M + sw) = Mv;
    }
}

// stage one tile's B splits (16KB over 256 threads, 64B each)
__device__ __forceinline__ void stage_B_half(int kt, u32 slotu, int tt) {
    if (tt < 128) {
        const unsigned char* s = g_Wh + kt * 8192 + tt * 64;
        u32 d = slotu + B_H + tt * 64;
        CP16(d, s); CP16(d+16, s+16); CP16(d+32, s+32); CP16(d+48, s+48);
    } else {
        int u = tt - 128;
        const unsigned char* s = g_Wm + kt * 8192 + u * 64;
        u32 d = slotu + B_M + u * 64;
        CP16(d, s); CP16(d+16, s+16); CP16(d+32, s+32); CP16(d+48, s+48);
    }
}

__device__ __forceinline__ void token_epilogue(
    const float* lg, int lane, int tl, int rowBase, float* out, int out_size,
    float& z_accum, float* comb, int* flagcnt, int* flaglist)
{
    float m1 = -1e30f, m2 = -1e30f, m3 = -1e30f; int i1 = 0, i2 = 0;
    #pragma unroll
    for (int j = 0; j < 16; j++) {
        int e = (j >> 1) * 8 + (lane & 3) * 2 + (j & 1);
        float v = lg[j];
        if (v > m1)      { m3 = m2; m2 = m1; i2 = i1; m1 = v; i1 = e; }
        else if (v > m2) { m3 = m2; m2 = v; i2 = e; }
        else if (v > m3) { m3 = v; }
    }
    #pragma unroll
    for (int off = 1; off <= 2; off <<= 1) {
        float om1 = __shfl_xor_sync(0xFFFFFFFFu, m1, off);
        float om2 = __shfl_xor_sync(0xFFFFFFFFu, m2, off);
        float om3 = __shfl_xor_sync(0xFFFFFFFFu, m3, off);
        int   oi1 = __shfl_xor_sync(0xFFFFFFFFu, i1, off);
        int   oi2 = __shfl_xor_sync(0xFFFFFFFFu, i2, off);
        if (om1 > m1) {
            float n2; int j2; float n3;
            if (m1 > om2) { n2 = m1; j2 = i1; n3 = fmaxf(om2, m2); }
            else          { n2 = om2; j2 = oi2; n3 = fmaxf(m1, om3); }
            m1 = om1; i1 = oi1; m2 = n2; i2 = j2; m3 = n3;
        } else {
            if (om1 > m2) { m3 = fmaxf(m2, om2); m2 = om1; i2 = oi1; }
            else          { m3 = fmaxf(om1, m3); }
        }
    }
    float s = 0.0f, ex[16];
    #pragma unroll
    for (int j = 0; j < 16; j++) { ex[j] = __expf(lg[j] - m1); s += ex[j]; }
    s += __shfl_xor_sync(0xFFFFFFFFu, s, 1);
    s += __shfl_xor_sync(0xFFFFFFFFu, s, 2);
    float invS = 1.0f / s;
    #pragma unroll
    for (int j = 0; j < 16; j++) comb[j] += ex[j] * invS;
    if ((lane & 3) == 0) {
        float lse = m1 + __logf(s);
        z_accum += lse * lse;
        float p1 = invS, p2 = __expf(m2 - m1) * invS;
        float r2 = 1.0f / (1.0f + __expf(p1 - p2));
        float r1 = 1.0f - r2;
        int gt = rowBase + tl;
        if (2 * gt + 1 < out_size) { out[2 * gt] = r1; out[2 * gt + 1] = r2; }
        int ib = 2 * NTOK;
        if (ib + 2 * gt + 1 < out_size) {
            out[ib + 2 * gt] = (float)i1; out[ib + 2 * gt + 1] = (float)i2;
        }
        if (m1 - m2 < GAP_TH || m2 - m3 < GAP_TH) {
            int slot = atomicAdd(flagcnt, 1);
            if (slot < 32) flaglist[slot] = tl;
        }
    }
}

__global__ __launch_bounds__(512, 1) void gate_kernel(
    const float* __restrict__ x, const float* __restrict__ Wg,
    float* __restrict__ out, int out_size)
{
    extern __shared__ __align__(128) unsigned char smc[];
    __shared__ float wsum[8][E];
    __shared__ float wz[8];
    __shared__ float redsm[512];
    __shared__ float zred2[4];
    __shared__ unsigned int lastflag;
    __shared__ int flagcnt;
    __shared__ int flaglist[32];

    const u32 smB = smem_u32(smc);
    const int tid = threadIdx.x;
    const int w = tid >> 5;
    const int lane = tid & 31;
    const int wl = w & 7;     // token group (16 tokens)
    const int wg = w >> 3;    // k-half (even/odd tiles)
    const int blk = blockIdx.x;
    const int rowBase = blk * TM;

    // conversion/staging mapping (512 threads)
    const int cvt_tile = tid & 1;
    const int tt = tid >> 1;          // 0..255
    const int cvt_row = tt >> 1;      // 0..127
    const int cvt_half = tt & 1;      // 32-col half

    if (tid == 0) flagcnt = 0;

    float acc[8][4];
    #pragma unroll
    for (int n = 0; n < 8; n++)
        #pragma unroll
        for (int j = 0; j < 4; j++) acc[n][j] = 0.0f;

    // ---- prologue: pairs 0 and 1 ----
    {
        float4 xr[8];
        const float4* s0 = (const float4*)(
            x + (size_t)(rowBase + cvt_row) * H + cvt_tile * 64 + cvt_half * 32);
        #pragma unroll
        for (int j = 0; j < 8; j++) xr[j] = s0[j];
        convert_store(xr, smc + SLOT(0, cvt_tile), cvt_row, cvt_half);
        stage_B_half(cvt_tile, smB + SLOT(0, cvt_tile), tt);
        CP_COMMIT();
        const float4* s1 = (const float4*)(
            x + (size_t)(rowBase + cvt_row) * H + (2 + cvt_tile) * 64 + cvt_half * 32);
        #pragma unroll
        for (int j = 0; j < 8; j++) xr[j] = s1[j];
        convert_store(xr, smc + SLOT(1, cvt_tile), cvt_row, cvt_half);
        stage_B_half(2 + cvt_tile, smB + SLOT(1, cvt_tile), tt);
        CP_COMMIT();
    }
    CP_WAIT1();
    __syncthreads();

    for (int ktp = 0; ktp < NPAIR; ktp++) {
        const int par = ktp & 1;
        const u32 slotu = smB + SLOT(par, wg);
        const int p2 = ktp + 2;
        float4 xr[8];
        if (p2 < NPAIR) {
            const float4* src = (const float4*)(
                x + (size_t)(rowBase + cvt_row) * H + (2 * p2 + cvt_tile) * 64 + cvt_half * 32);
            #pragma unroll
            for (int j = 0; j < 8; j++) xr[j] = src[j];
        }

        compute_tile(slotu, acc, wl, lane);
        __syncthreads();   // all warps done reading pair ktp slots

        if (p2 < NPAIR) {
            convert_store(xr, smc + SLOT(par, cvt_tile), cvt_row, cvt_half);
            stage_B_half(2 * p2 + cvt_tile, smB + SLOT(par, cvt_tile), tt);
            CP_COMMIT();
            CP_WAIT1();    // pair ktp+1 B complete
        } else if (ktp + 1 < NPAIR) {
            CP_WAIT0();
        }
        __syncthreads();
    }

    // ---- split-K merge: wg1 -> smem -> wg0 adds ----
    float* exch = (float*)smc;
    if (wg == 1) {
        #pragma unroll
        for (int n = 0; n < 8; n++)
            #pragma unroll
            for (int j = 0; j < 4; j++)
                exch[(wl * 32 + lane) * 32 + n * 4 + j] = acc[n][j];
    }
    __syncthreads();

    if (wg == 0) {
        #pragma unroll
        for (int n = 0; n < 8; n++)
            #pragma unroll
            for (int j = 0; j < 4; j++)
                acc[n][j] += exch[(wl * 32 + lane) * 32 + n * 4 + j];

        float lgl[16], lgh[16];
        #pragma unroll
        for (int n = 0; n < 8; n++) {
            lgl[2*n] = acc[n][0]; lgl[2*n+1] = acc[n][1];
            lgh[2*n] = acc[n][2]; lgh[2*n+1] = acc[n][3];
        }
        float comb[16];
        #pragma unroll
        for (int j = 0; j < 16; j++) comb[j] = 0.0f;
        float zacc = 0.0f;

        int tl_lo = wl * 16 + (lane >> 2);
        token_epilogue(lgl, lane, tl_lo,     rowBase, out, out_size, zacc, comb, &flagcnt, flaglist);
        token_epilogue(lgh, lane, tl_lo + 8, rowBase, out, out_size, zacc, comb, &flagcnt, flaglist);

        #pragma unroll
        for (int off = 4; off <= 16; off <<= 1)
            #pragma unroll
            for (int j = 0; j < 16; j++)
                comb[j] += __shfl_down_sync(0xFFFFFFFFu, comb[j], off);
        if (lane < 4) {
            #pragma unroll
            for (int j = 0; j < 16; j++)
                wsum[wl][(j >> 1) * 8 + lane * 2 + (j & 1)] = comb[j];
        }
        float zs = zacc;
        #pragma unroll
        for (int off = 16; off > 0; off >>= 1)
            zs += __shfl_down_sync(0xFFFFFFFFu, zs, off);
        if (lane == 0) wz[wl] = zs;
    }
    __syncthreads();

    // ---- exact fp32 recompute for near-tie tokens (all 512 threads) ----
    {
        int nf = flagcnt; if (nf > 32) nf = 32;
        for (int f = 0; f < nf; f++) {
            int tl = flaglist[f];
            int gt = rowBase + tl;
            const float4* xr4 = (const float4*)(x + (size_t)gt * H);
            const float4* wr4 = (const float4*)(Wg + (size_t)(tid & 63) * H);
            int q = tid >> 6;   // 0..7
            float s0 = 0.f, s1 = 0.f, s2 = 0.f, s3 = 0.f;
            #pragma unroll 4
            for (int k = q * 64; k < q * 64 + 64; k++) {
                float4 xv = xr4[k], wv = wr4[k];
                s0 += xv.x * wv.x; s1 += xv.y * wv.y;
                s2 += xv.z * wv.z; s3 += xv.w * wv.w;
            }
            redsm[tid] = (s0 + s1) + (s2 + s3);
            __syncthreads();
            if (tid == 0) {
                float m1 = -1e30f, m2 = -1e30f; int i1 = 0, i2 = 0;
                for (int e = 0; e < E; e++) {
                    float v = 0.0f;
                    #pragma unroll
                    for (int qq = 0; qq < 8; qq++) v += redsm[qq * 64 + e];
                    redsm[e] = v;
                    if (v > m1) { m2 = m1; i2 = i1; m1 = v; i1 = e; }
                    else if (v > m2) { m2 = v; i2 = e; }
                }
                float s = 0.0f;
                for (int e = 0; e < E; e++) s += __expf(redsm[e] - m1);
                float inv = 1.0f / s;
                float p1 = inv, p2 = __expf(m2 - m1) * inv;
                float r2 = 1.0f / (1.0f + __expf(p1 - p2));
                float r1 = 1.0f - r2;
                if (2 * gt + 1 < out_size) { out[2 * gt] = r1; out[2 * gt + 1] = r2; }
                int ib = 2 * NTOK;
                if (ib + 2 * gt + 1 < out_size) {
                    out[ib + 2 * gt] = (float)i1; out[ib + 2 * gt + 1] = (float)i2;
                }
            }
            __syncthreads();
        }
    }

    if (tid < E) {
        float s = 0.0f;
        #pragma unroll
        for (int ww = 0; ww < 8; ww++) s += wsum[ww][tid];
        g_part_load[blk * E + tid] = s;
    }
    if (tid == 0) {
        float z = 0.0f;
        #pragma unroll
        for (int ww = 0; ww < 8; ww++) z += wz[ww];
        g_part_z[blk] = z;
    }

    // ---- last-block loss reduction ----
    __threadfence();
    __syncthreads();
    if (tid == 0) {
        unsigned int v = atomicAdd(&g_arrive, 1u);
        lastflag = (v == NBLK - 1) ? 1u : 0u;
    }
    __syncthreads();
    if (lastflag) {
        __threadfence();
        int qq = tid >> 6, e = tid & 63;
        float sacc = 0.0f;
        for (int b = qq * 16; b < qq * 16 + 16; b++) sacc += g_part_load[b * E + e];
        redsm[tid] = sacc;
        __syncthreads();
        if (tid < E) {
            float S = 0.0f;
            #pragma unroll
            for (int q2 = 0; q2 < 8; q2++) S += redsm[q2 * 64 + tid];
            float d = S * (1.0f / (float)NTOK) - (1.0f / (float)E);
            redsm[tid] = d * d;
        }
        __syncthreads();
        if (tid < 32) {
            float v = redsm[tid] + redsm[tid + 32];
            #pragma unroll
            for (int o = 16; o > 0; o >>= 1) v += __shfl_down_sync(0xFFFFFFFFu, v, o);
            if (tid == 0) redsm[0] = v;  // lb sum
        }
        if (tid >= 128 && tid < 256) {
            float zv = g_part_z[tid - 128];
            #pragma unroll
            for (int o = 16; o > 0; o >>= 1) zv += __shfl_down_sync(0xFFFFFFFFu, zv, o);
            if (((tid - 128) & 31) == 0) zred2[(tid - 128) >> 5] = zv;
        }
        __syncthreads();
        if (tid == 0) {
            float z = zred2[0] + zred2[1] + zred2[2] + zred2[3];
            float total = 0.01f * redsm[0] + 1e-4f * (z / (float)NTOK);
            if (out_size > 4 * NTOK) out[4 * NTOK] = total;
            g_arrive = 0;
        }
    }
}

extern "C" void kernel_launch(void* const* d_in, const int* in_sizes, int n_in,
                              void* d_out, int out_size)
{
    const float* x = (const float*)d_in[0];
    const float* W = (const float*)d_in[1];
    float* out = (float*)d_out;

    cudaFuncSetAttribute(gate_kernel, cudaFuncAttributeMaxDynamicSharedMemorySize, SMEM_DYN);
    prep_kernel<<<E, 256>>>(W);
    gate_kernel<<<NBLK, 512, SMEM_DYN>>>(x, W, out, out_size);
}

// round 11
// speedup vs baseline: 1.3884x; 1.3884x over previous
#include <cuda_runtime.h>
#include <cuda_bf16.h>

#define H      2048
#define E      64
#define NTOK   16384
#define TM     128
#define NBLK   128
#define NKT    32

typedef unsigned int u32;

// -------- device scratch (allocation-free) --------
__device__ __align__(16) unsigned char g_Wh[NKT * 8192];
__device__ __align__(16) unsigned char g_Wm[NKT * 8192];
__device__ __align__(16) unsigned char g_Wl[NKT * 8192];
__device__ float g_part_load[NBLK * E];
__device__ float g_part_z[NBLK];
__device__ unsigned int g_arrive = 0;

#define SWZ(o) ((o) ^ (((o) >> 3) & 0x70))

// smem rings: x fp32 tiles (stride 72 floats = 288B, conflict-free LDS.64 phases)
#define XSTR   288
#define XTILE  (TM * XSTR)            // 36864
#define X_OFF(s) ((s) * XTILE)        // 3 slots: 110592
#define BTILE  24576                  // h/m/l bf16 splits, 8KB each
#define B_OFF(s) (110592 + (s) * BTILE)   // 3 slots: 73728
#define SMEM_DYN (110592 + 73728)     // 184320

__device__ __forceinline__ u32 smem_u32(const void* p) {
    u32 a;
    asm("{ .reg .u64 t; cvta.to.shared.u64 t, %1; cvt.u32.u64 %0, t; }" : "=r"(a) : "l"(p));
    return a;
}

#define CP16(dst, src) \
    asm volatile("cp.async.cg.shared.global [%0], [%1], 16;" :: "r"(dst), "l"(src) : "memory")
#define CP_COMMIT() asm volatile("cp.async.commit_group;" ::: "memory")
#define CP_WAIT0()  asm volatile("cp.async.wait_group 0;" ::: "memory")
#define CP_WAIT1()  asm volatile("cp.async.wait_group 1;" ::: "memory")
#define CP_WAIT2()  asm volatile("cp.async.wait_group 2;" ::: "memory")

#define LDSM4(r0, r1, r2, r3, addr) \
    asm volatile("ldmatrix.sync.aligned.m8n8.x4.shared.b16 {%0,%1,%2,%3}, [%4];" \
        : "=r"(r0), "=r"(r1), "=r"(r2), "=r"(r3) : "r"(addr))

#define MMA(d, a, b0, b1) \
    asm volatile("mma.sync.aligned.m16n8k16.row.col.f32.bf16.bf16.f32 " \
        "{%0,%1,%2,%3}, {%4,%5,%6,%7}, {%8,%9}, {%0,%1,%2,%3};" \
        : "+f"((d)[0]), "+f"((d)[1]), "+f"((d)[2]), "+f"((d)[3]) \
        : "r"((a)[0]), "r"((a)[1]), "r"((a)[2]), "r"((a)[3]), "r"(b0), "r"(b1))

// 3-way bf16 split of a float pair (residuals exact in fp32)
__device__ __forceinline__ void split3(float a, float b, u32& h, u32& m, u32& l) {
    __nv_bfloat162 hb = __floats2bfloat162_rn(a, b);
    float2 hf = __bfloat1622float2(hb);
    float ra = a - hf.x, rb = b - hf.y;
    __nv_bfloat162 mb = __floats2bfloat162_rn(ra, rb);
    float2 mf = __bfloat1622float2(mb);
    __nv_bfloat162 lb = __floats2bfloat162_rn(ra - mf.x, rb - mf.y);
    h = *(u32*)&hb; m = *(u32*)&mb; l = *(u32*)&lb;
}

// -------- prep: split + pre-swizzle W into per-tile bf16 arrays --------
__global__ __launch_bounds__(256) void prep_kernel(const float* __restrict__ W) {
    int e = blockIdx.x;
    int t = threadIdx.x;
    int k0 = t * 8;
    int kt = k0 >> 6;
    int c  = k0 & 63;
    const float4* src = (const float4*)(W + (size_t)e * H + k0);
    float4 a = src[0], b = src[1];
    uint4 Hv, Mv, Lv;
    split3(a.x, a.y, Hv.x, Mv.x, Lv.x);
    split3(a.z, a.w, Hv.y, Mv.y, Lv.y);
    split3(b.x, b.y, Hv.z, Mv.z, Lv.z);
    split3(b.z, b.w, Hv.w, Mv.w, Lv.w);
    u32 off = kt * 8192 + SWZ((u32)(e * 128 + c * 2));
    *(uint4*)(g_Wh + off) = Hv;
    *(uint4*)(g_Wm + off) = Mv;
    *(uint4*)(g_Wl + off) = Lv;
}

__device__ __forceinline__ void pass8(float (*acc)[4], const u32* a, const u32* b) {
    #pragma unroll
    for (int g = 0; g < 4; g++) {
        MMA(acc[2*g],   a, b[4*g],   b[4*g+1]);
        MMA(acc[2*g+1], a, b[4*g+2], b[4*g+3]);
    }
}
__device__ __forceinline__ void ldsm_grp(u32* b, u32 base, int c, int rowpart, int kb16) {
    #pragma unroll
    for (int g = 0; g < 4; g++) {
        u32 off = (u32)((g * 16 + rowpart) * 128 + c * 32 + kb16);
        LDSM4(b[4*g], b[4*g+1], b[4*g+2], b[4*g+3], base + SWZ(off));
    }
}

// chunk body: X holds h-split(c) on entry; leaves h-split(c+1) in Y.
#define CHUNK(c, X, Y) do {                                                   \
    u32 ah[4], am[4], al[4];                                                  \
    {                                                                         \
        float2 p0 = *(const float2*)(xl + (c) * 64);                          \
        float2 p1 = *(const float2*)(xh + (c) * 64);                          \
        float2 p2 = *(const float2*)(xl + (c) * 64 + 32);                     \
        float2 p3 = *(const float2*)(xh + (c) * 64 + 32);                     \
        split3(p0.x, p0.y, ah[0], am[0], al[0]);                              \
        split3(p1.x, p1.y, ah[1], am[1], al[1]);                              \
        split3(p2.x, p2.y, ah[2], am[2], al[2]);                              \
        split3(p3.x, p3.y, ah[3], am[3], al[3]);                              \
    }                                                                         \
    ldsm_grp(Y, bbase + 8192, (c), rowpart, kb16);      /* m-split */         \
    pass8(acc, ah, X); pass8(acc, am, X); pass8(acc, al, X);  /* x * Wh */    \
    ldsm_grp(X, bbase + 16384, (c), rowpart, kb16);     /* l-split */         \
    pass8(acc, ah, Y); pass8(acc, am, Y);                     /* x * Wm */    \
    if ((c) < 3) ldsm_grp(Y, bbase, (c) + 1, rowpart, kb16); /* next h */     \
    pass8(acc, ah, X);                                        /* xh * Wl */   \
} while (0)

// stage pre-swizzled B splits for tile kt (24 KB, 6 CP16/thread)
__device__ __forceinline__ void stage_B(int kt, u32 smDst, int tid) {
    u32 d = smDst + tid * 32;
    const unsigned char* s;
    s = g_Wh + kt * 8192 + tid * 32; CP16(d, s);          CP16(d + 16, s + 16);
    s = g_Wm + kt * 8192 + tid * 32; CP16(d + 8192, s);   CP16(d + 8192 + 16, s + 16);
    s = g_Wl + kt * 8192 + tid * 32; CP16(d + 16384, s);  CP16(d + 16384 + 16, s + 16);
}

// stage fp32 x tile kt (32 KB, 8 CP16/thread): row = tid>>1, half = tid&1
__device__ __forceinline__ void stage_x(
    const float* __restrict__ x, int rowBase, int kt, u32 smDst, int tid)
{
    int row = tid >> 1, half = tid & 1;
    const float* s = x + (size_t)(rowBase + row) * H + kt * 64 + half * 32;
    u32 d = smDst + row * XSTR + half * 128;
    #pragma unroll
    for (int j = 0; j < 8; j++) CP16(d + j * 16, s + j * 4);
}

__device__ __forceinline__ void token_epilogue(
    const float* lg, int lane, int gt, float* out, int out_size,
    float& z_accum, float* comb)
{
    float m1 = -1e30f, m2 = -1e30f; int i1 = 0, i2 = 0;
    #pragma unroll
    for (int j = 0; j < 16; j++) {
        int e = (j >> 1) * 8 + (lane & 3) * 2 + (j & 1);
        float v = lg[j];
        if (v > m1) { m2 = m1; i2 = i1; m1 = v; i1 = e; }
        else if (v > m2) { m2 = v; i2 = e; }
    }
    #pragma unroll
    for (int off = 1; off <= 2; off <<= 1) {
        float om1 = __shfl_xor_sync(0xFFFFFFFFu, m1, off);
        float om2 = __shfl_xor_sync(0xFFFFFFFFu, m2, off);
        int   oi1 = __shfl_xor_sync(0xFFFFFFFFu, i1, off);
        int   oi2 = __shfl_xor_sync(0xFFFFFFFFu, i2, off);
        if (om1 > m1) {
            float t2; int tj2;
            if (m1 > om2) { t2 = m1; tj2 = i1; } else { t2 = om2; tj2 = oi2; }
            m1 = om1; i1 = oi1; m2 = t2; i2 = tj2;
        } else if (om1 > m2) { m2 = om1; i2 = oi1; }
    }
    float s = 0.0f, ex[16];
    #pragma unroll
    for (int j = 0; j < 16; j++) { ex[j] = __expf(lg[j] - m1); s += ex[j]; }
    s += __shfl_xor_sync(0xFFFFFFFFu, s, 1);
    s += __shfl_xor_sync(0xFFFFFFFFu, s, 2);
    float invS = 1.0f / s;
    #pragma unroll
    for (int j = 0; j < 16; j++) comb[j] += ex[j] * invS;
    if ((lane & 3) == 0) {
        float lse = m1 + __logf(s);
        z_accum += lse * lse;
        // softmax over the top-2 PROBABILITIES (p1 = 1/S, p2 = exp(m2-m1)/S)
        float p1 = invS, p2 = __expf(m2 - m1) * invS;
        float r2 = 1.0f / (1.0f + __expf(p1 - p2));
        float r1 = 1.0f - r2;
        if (2 * gt + 1 < out_size) { out[2 * gt] = r1; out[2 * gt + 1] = r2; }
        int ib = 2 * NTOK;
        if (ib + 2 * gt + 1 < out_size) {
            out[ib + 2 * gt] = (float)i1; out[ib + 2 * gt + 1] = (float)i2;
        }
    }
}

__global__ __launch_bounds__(256, 1) void gate_kernel(
    const float* __restrict__ x, float* __restrict__ out, int out_size)
{
    extern __shared__ __align__(128) unsigned char smc[];
    __shared__ float wsum[8][E];
    __shared__ float wz[8];
    __shared__ float redsm[256];
    __shared__ float zred2[4];
    __shared__ unsigned int lastflag;

    const u32 smB = smem_u32(smc);
    const int tid = threadIdx.x;
    const int w = tid >> 5;
    const int lane = tid & 31;
    const int blk = blockIdx.x;
    const int rowBase = blk * TM;

    const int rowpart = ((lane >> 4) & 1) * 8 + (lane & 7);
    const int kb16    = ((lane >> 3) & 1) * 16;
    // per-warp x read base (this lane's token rows)
    const u32 xrow_l = (u32)((w * 16 + (lane >> 2)) * XSTR + (lane & 3) * 8);
    const u32 xrow_h = xrow_l + 8 * XSTR;

    float acc[8][4];
    #pragma unroll
    for (int n = 0; n < 8; n++)
        #pragma unroll
        for (int j = 0; j < 4; j++) acc[n][j] = 0.0f;

    // ---- prologue: stage tiles 0..2 (one commit group each) ----
    #pragma unroll
    for (int p = 0; p < 3; p++) {
        stage_x(x, rowBase, p, smB + X_OFF(p), tid);
        stage_B(p, smB + B_OFF(p), tid);
        CP_COMMIT();
    }
    CP_WAIT2();        // tile 0 complete (1,2 may be in flight)
    __syncthreads();

    for (int kt = 0; kt < NKT; kt++) {
        const int slot = kt % 3;
        const unsigned char* xl = smc + X_OFF(slot) + xrow_l;
        const unsigned char* xh = smc + X_OFF(slot) + xrow_h;
        const u32 bbase = smB + B_OFF(slot);

        {
            u32 b0[16], b1[16];
            ldsm_grp(b0, bbase, 0, rowpart, kb16);   // h-split, chunk 0
            CHUNK(0, b0, b1);
            CHUNK(1, b1, b0);
            CHUNK(2, b0, b1);
            CHUNK(3, b1, b0);
        }
        __syncthreads();   // all warps done with slot kt%3

        if (kt + 3 < NKT) {
            stage_x(x, rowBase, kt + 3, smB + X_OFF(slot), tid);
            stage_B(kt + 3, smB + B_OFF(slot), tid);
            CP_COMMIT();
        }
        if (kt + 1 < NKT) {
            if (kt + 3 < NKT)      CP_WAIT2();   // tile kt+1 complete
            else if (kt + 2 < NKT) CP_WAIT1();
            else                   CP_WAIT0();
            __syncthreads();
        }
    }

    // -------- epilogue --------
    float lgl[16], lgh[16];
    #pragma unroll
    for (int n = 0; n < 8; n++) {
        lgl[2*n] = acc[n][0]; lgl[2*n+1] = acc[n][1];
        lgh[2*n] = acc[n][2]; lgh[2*n+1] = acc[n][3];
    }

    float comb[16];
    #pragma unroll
    for (int j = 0; j < 16; j++) comb[j] = 0.0f;
    float zacc = 0.0f;

    int gt_lo = rowBase + w * 16 + (lane >> 2);
    token_epilogue(lgl, lane, gt_lo,     out, out_size, zacc, comb);
    token_epilogue(lgh, lane, gt_lo + 8, out, out_size, zacc, comb);

    // warp reduce expert prob sums across quads (tokens)
    #pragma unroll
    for (int off = 4; off <= 16; off <<= 1)
        #pragma unroll
        for (int j = 0; j < 16; j++)
            comb[j] += __shfl_down_sync(0xFFFFFFFFu, comb[j], off);
    if (lane < 4) {
        #pragma unroll
        for (int j = 0; j < 16; j++)
            wsum[w][(j >> 1) * 8 + lane * 2 + (j & 1)] = comb[j];
    }
    float zs = zacc;
    #pragma unroll
    for (int off = 16; off > 0; off >>= 1)
        zs += __shfl_down_sync(0xFFFFFFFFu, zs, off);
    if (lane == 0) wz[w] = zs;
    __syncthreads();

    if (tid < E) {
        float s = 0.0f;
        #pragma unroll
        for (int ww = 0; ww < 8; ww++) s += wsum[ww][tid];
        g_part_load[blk * E + tid] = s;
    }
    if (tid == 0) {
        float z = 0.0f;
        #pragma unroll
        for (int ww = 0; ww < 8; ww++) z += wz[ww];
        g_part_z[blk] = z;
    }

    // -------- last-block loss reduction --------
    __threadfence();
    __syncthreads();
    if (tid == 0) {
        unsigned int v = atomicAdd(&g_arrive, 1u);
        lastflag = (v == NBLK - 1) ? 1u : 0u;
    }
    __syncthreads();
    if (lastflag) {
        __threadfence();
        int qq = tid >> 6, e = tid & 63;
        float sacc = 0.0f;
        for (int b = qq * 32; b < qq * 32 + 32; b++) sacc += g_part_load[b * E + e];
        redsm[tid] = sacc;
        __syncthreads();
        if (tid < E) {
            float S = redsm[tid] + redsm[64 + tid] + redsm[128 + tid] + redsm[192 + tid];
            float d = S * (1.0f / (float)NTOK) - (1.0f / (float)E);
            redsm[tid] = d * d;
        }
        __syncthreads();
        if (tid < 32) {
            float v = redsm[tid] + redsm[tid + 32];
            #pragma unroll
            for (int o = 16; o > 0; o >>= 1) v += __shfl_down_sync(0xFFFFFFFFu, v, o);
            if (tid == 0) redsm[0] = v;  // lb sum
        }
        if (tid >= 128 && tid < 256) {
            float zv = g_part_z[tid - 128];
            #pragma unroll
            for (int o = 16; o > 0; o >>= 1) zv += __shfl_down_sync(0xFFFFFFFFu, zv, o);
            if (((tid - 128) & 31) == 0) zred2[(tid - 128) >> 5] = zv;
        }
        __syncthreads();
        if (tid == 0) {
            float z = zred2[0] + zred2[1] + zred2[2] + zred2[3];
            float total = 0.01f * redsm[0] + 1e-4f * (z / (float)NTOK);
            if (out_size > 4 * NTOK) out[4 * NTOK] = total;
            g_arrive = 0;
        }
    }
}

extern "C" void kernel_launch(void* const* d_in, const int* in_sizes, int n_in,
                              void* d_out, int out_size)
{
    const float* x = (const float*)d_in[0];
    const float* W = (const float*)d_in[1];
    float* out = (float*)d_out;

    cudaFuncSetAttribute(gate_kernel, cudaFuncAttributeMaxDynamicSharedMemorySize, SMEM_DYN);
    prep_kernel<<<E, 256>>>(W);
    gate_kernel<<<NBLK, 256, SMEM_DYN>>>(x, out, out_size);
}

// round 12
// speedup vs baseline: 1.4129x; 1.0177x over previous
#include <cuda_runtime.h>
#include <cuda_bf16.h>

#define H      2048
#define E      64
#define NTOK   16384
#define TM     128
#define NBLK   128
#define NKT    32

typedef unsigned int u32;

// -------- device scratch (allocation-free) --------
__device__ __align__(16) unsigned char g_Wh[NKT * 8192];
__device__ __align__(16) unsigned char g_Wm[NKT * 8192];
__device__ __align__(16) unsigned char g_Wl[NKT * 8192];
__device__ float g_part_load[NBLK * E];
__device__ float g_part_z[NBLK];
__device__ unsigned int g_arrive = 0;

#define SWZ(o) ((o) ^ (((o) >> 3) & 0x70))

// smem rings: x fp32 tiles (stride 72 floats) + B bf16 split tiles
#define XSTR   288
#define XTILE  (TM * XSTR)                 // 36864
#define X_OFF(s) ((s) * XTILE)             // 3 slots: 110592
#define BTILE  24576
#define B_OFF(s) (110592 + (s) * BTILE)    // 3 slots: 73728
#define SMEM_DYN (110592 + 73728)          // 184320

__device__ __forceinline__ u32 smem_u32(const void* p) {
    u32 a;
    asm("{ .reg .u64 t; cvta.to.shared.u64 t, %1; cvt.u32.u64 %0, t; }" : "=r"(a) : "l"(p));
    return a;
}

#define CP16(dst, src) \
    asm volatile("cp.async.cg.shared.global [%0], [%1], 16;" :: "r"(dst), "l"(src) : "memory")
#define CP_COMMIT() asm volatile("cp.async.commit_group;" ::: "memory")
#define CP_WAIT0()  asm volatile("cp.async.wait_group 0;" ::: "memory")
#define CP_WAIT1()  asm volatile("cp.async.wait_group 1;" ::: "memory")
#define CP_WAIT2()  asm volatile("cp.async.wait_group 2;" ::: "memory")

#define LDSM4(r0, r1, r2, r3, addr) \
    asm volatile("ldmatrix.sync.aligned.m8n8.x4.shared.b16 {%0,%1,%2,%3}, [%4];" \
        : "=r"(r0), "=r"(r1), "=r"(r2), "=r"(r3) : "r"(addr))

#define MMA(d, a, b0, b1) \
    asm volatile("mma.sync.aligned.m16n8k16.row.col.f32.bf16.bf16.f32 " \
        "{%0,%1,%2,%3}, {%4,%5,%6,%7}, {%8,%9}, {%0,%1,%2,%3};" \
        : "+f"((d)[0]), "+f"((d)[1]), "+f"((d)[2]), "+f"((d)[3]) \
        : "r"((a)[0]), "r"((a)[1]), "r"((a)[2]), "r"((a)[3]), "r"(b0), "r"(b1))

// 3-way bf16 split of a float pair (residuals exact in fp32)
__device__ __forceinline__ void split3(float a, float b, u32& h, u32& m, u32& l) {
    __nv_bfloat162 hb = __floats2bfloat162_rn(a, b);
    float2 hf = __bfloat1622float2(hb);
    float ra = a - hf.x, rb = b - hf.y;
    __nv_bfloat162 mb = __floats2bfloat162_rn(ra, rb);
    float2 mf = __bfloat1622float2(mb);
    __nv_bfloat162 lb = __floats2bfloat162_rn(ra - mf.x, rb - mf.y);
    h = *(u32*)&hb; m = *(u32*)&mb; l = *(u32*)&lb;
}

// -------- prep: split + pre-swizzle W into per-tile bf16 arrays --------
__global__ __launch_bounds__(256) void prep_kernel(const float* __restrict__ W) {
    int e = blockIdx.x;
    int t = threadIdx.x;
    int k0 = t * 8;
    int kt = k0 >> 6;
    int c  = k0 & 63;
    const float4* src = (const float4*)(W + (size_t)e * H + k0);
    float4 a = src[0], b = src[1];
    uint4 Hv, Mv, Lv;
    split3(a.x, a.y, Hv.x, Mv.x, Lv.x);
    split3(a.z, a.w, Hv.y, Mv.y, Lv.y);
    split3(b.x, b.y, Hv.z, Mv.z, Lv.z);
    split3(b.z, b.w, Hv.w, Mv.w, Lv.w);
    u32 off = kt * 8192 + SWZ((u32)(e * 128 + c * 2));
    *(uint4*)(g_Wh + off) = Hv;
    *(uint4*)(g_Wm + off) = Mv;
    *(uint4*)(g_Wl + off) = Lv;
}

__device__ __forceinline__ void pass4(float (*acc)[4], const u32* a, const u32* b) {
    MMA(acc[0], a, b[0], b[1]); MMA(acc[1], a, b[2], b[3]);
    MMA(acc[2], a, b[4], b[5]); MMA(acc[3], a, b[6], b[7]);
}
// B fragments for this warp's 32 experts (2 x 16-row groups)
__device__ __forceinline__ void ldsm_b2(u32* b, u32 base, int c, int we, int rowpart, int kb16) {
    #pragma unroll
    for (int g = 0; g < 2; g++) {
        u32 off = (u32)((we * 32 + g * 16 + rowpart) * 128 + c * 32 + kb16);
        LDSM4(b[4*g], b[4*g+1], b[4*g+2], b[4*g+3], base + SWZ(off));
    }
}

// chunk body: X holds h-split(c) on entry; leaves h-split(c+1) in Y.
#define CHUNK(c, X, Y) do {                                                   \
    u32 ah[4], am[4], al[4];                                                  \
    {                                                                         \
        float2 p0 = *(const float2*)(xl + (c) * 64);                          \
        float2 p1 = *(const float2*)(xh + (c) * 64);                          \
        float2 p2 = *(const float2*)(xl + (c) * 64 + 32);                     \
        float2 p3 = *(const float2*)(xh + (c) * 64 + 32);                     \
        split3(p0.x, p0.y, ah[0], am[0], al[0]);                              \
        split3(p1.x, p1.y, ah[1], am[1], al[1]);                              \
        split3(p2.x, p2.y, ah[2], am[2], al[2]);                              \
        split3(p3.x, p3.y, ah[3], am[3], al[3]);                              \
    }                                                                         \
    ldsm_b2(Y, bbase + 8192, (c), we, rowpart, kb16);      /* m-split */      \
    pass4(acc, ah, X); pass4(acc, am, X); pass4(acc, al, X);                  \
    ldsm_b2(X, bbase + 16384, (c), we, rowpart, kb16);     /* l-split */      \
    pass4(acc, ah, Y); pass4(acc, am, Y);                                     \
    if ((c) < 3) ldsm_b2(Y, bbase, (c) + 1, we, rowpart, kb16);               \
    pass4(acc, ah, X);                                                        \
} while (0)

// stage pre-swizzled B splits for tile kt (24 KB, 3 CP16 per 512 threads)
__device__ __forceinline__ void stage_B(int kt, u32 smDst, int tid) {
    CP16(smDst + tid * 16,         g_Wh + kt * 8192 + tid * 16);
    CP16(smDst + 8192 + tid * 16,  g_Wm + kt * 8192 + tid * 16);
    CP16(smDst + 16384 + tid * 16, g_Wl + kt * 8192 + tid * 16);
}

// stage fp32 x tile kt (32 KB, 4 CP16/thread): row = tid>>2, quarter = tid&3
__device__ __forceinline__ void stage_x(
    const float* __restrict__ x, int rowBase, int kt, u32 smDst, int tid)
{
    int row = tid >> 2, q = tid & 3;
    const float* s = x + (size_t)(rowBase + row) * H + kt * 64 + q * 16;
    u32 d = smDst + row * XSTR + q * 64;
    CP16(d, s); CP16(d + 16, s + 4); CP16(d + 32, s + 8); CP16(d + 48, s + 12);
}

__global__ __launch_bounds__(512, 1) void gate_kernel(
    const float* __restrict__ x, float* __restrict__ out, int out_size)
{
    extern __shared__ __align__(128) unsigned char smc[];
    __shared__ float zsm[TM];
    __shared__ float redsm[512];
    __shared__ float zred2[4];
    __shared__ unsigned int lastflag;

    const u32 smB = smem_u32(smc);
    const int tid = threadIdx.x;
    const int w = tid >> 5;
    const int lane = tid & 31;
    const int wt = w & 7;      // token group (16 tokens)
    const int we = w >> 3;     // expert half (32 experts)
    const int blk = blockIdx.x;
    const int rowBase = blk * TM;

    const int rowpart = ((lane >> 4) & 1) * 8 + (lane & 7);
    const int kb16    = ((lane >> 3) & 1) * 16;
    const u32 xrow_l = (u32)((wt * 16 + (lane >> 2)) * XSTR + (lane & 3) * 8);
    const u32 xrow_h = xrow_l + 8 * XSTR;

    float acc[4][4];
    #pragma unroll
    for (int n = 0; n < 4; n++)
        #pragma unroll
        for (int j = 0; j < 4; j++) acc[n][j] = 0.0f;

    // ---- prologue: stage tiles 0..2 ----
    #pragma unroll
    for (int p = 0; p < 3; p++) {
        stage_x(x, rowBase, p, smB + X_OFF(p), tid);
        stage_B(p, smB + B_OFF(p), tid);
        CP_COMMIT();
    }
    CP_WAIT2();
    __syncthreads();

    for (int kt = 0; kt < NKT; kt++) {
        const int slot = kt % 3;
        const unsigned char* xl = smc + X_OFF(slot) + xrow_l;
        const unsigned char* xh = smc + X_OFF(slot) + xrow_h;
        const u32 bbase = smB + B_OFF(slot);

        {
            u32 b0[8], b1[8];
            ldsm_b2(b0, bbase, 0, we, rowpart, kb16);   // h-split, chunk 0
            CHUNK(0, b0, b1);
            CHUNK(1, b1, b0);
            CHUNK(2, b0, b1);
            CHUNK(3, b1, b0);
        }
        __syncthreads();   // all warps done with slot kt%3

        if (kt + 3 < NKT) {
            stage_x(x, rowBase, kt + 3, smB + X_OFF(slot), tid);
            stage_B(kt + 3, smB + B_OFF(slot), tid);
            CP_COMMIT();
        }
        if (kt + 1 < NKT) {
            if (kt + 3 < NKT)      CP_WAIT2();
            else if (kt + 2 < NKT) CP_WAIT1();
            else                   CP_WAIT0();
            __syncthreads();
        }
    }

    // -------- epilogue: logits -> smem [128][66] --------
    float* sc = (float*)smc;
    {
        const int r0 = wt * 16 + (lane >> 2);
        #pragma unroll
        for (int g = 0; g < 4; g++) {
            int e = we * 32 + g * 8 + (lane & 3) * 2;
            *(float2*)(sc + r0 * 66 + e)       = make_float2(acc[g][0], acc[g][1]);
            *(float2*)(sc + (r0 + 8) * 66 + e) = make_float2(acc[g][2], acc[g][3]);
        }
    }
    __syncthreads();

    if (tid < TM) {
        float* row = sc + tid * 66;
        float m1 = -1e30f, m2 = -1e30f; int i1 = 0, i2 = 0;
        #pragma unroll 8
        for (int e = 0; e < E; e++) {
            float v = row[e];
            if (v > m1) { m2 = m1; i2 = i1; m1 = v; i1 = e; }
            else if (v > m2) { m2 = v; i2 = e; }
        }
        float s = 0.0f;
        #pragma unroll 8
        for (int e = 0; e < E; e++) { float u = __expf(row[e] - m1); row[e] = u; s += u; }
        float inv = 1.0f / s;
        #pragma unroll 8
        for (int e = 0; e < E; e++) row[e] *= inv;    // normalized probs for lb loss
        float lse = m1 + __logf(s);
        zsm[tid] = lse * lse;

        // softmax over the top-2 PROBABILITIES (p1 = 1/S, p2 = exp(m2-m1)/S)
        float p1 = inv, p2 = __expf(m2 - m1) * inv;
        float r2 = 1.0f / (1.0f + __expf(p1 - p2));
        float r1 = 1.0f - r2;

        int gt = rowBase + tid;
        if (2 * gt + 1 < out_size) { out[2 * gt] = r1; out[2 * gt + 1] = r2; }
        int ib = 2 * NTOK;
        if (ib + 2 * gt + 1 < out_size) {
            out[ib + 2 * gt] = (float)i1; out[ib + 2 * gt + 1] = (float)i2;
        }
    }
    __syncthreads();

    if (tid < E) {
        float s = 0.0f;
        #pragma unroll 8
        for (int t = 0; t < TM; t++) s += sc[t * 66 + tid];
        g_part_load[blk * E + tid] = s;
    }
    if (tid == E) {
        float z = 0.0f;
        #pragma unroll 8
        for (int t = 0; t < TM; t++) z += zsm[t];
        g_part_z[blk] = z;
    }

    // -------- last-block loss reduction --------
    __threadfence();
    __syncthreads();
    if (tid == 0) {
        unsigned int v = atomicAdd(&g_arrive, 1u);
        lastflag = (v == NBLK - 1) ? 1u : 0u;
    }
    __syncthreads();
    if (lastflag) {
        __threadfence();
        int qq = tid >> 6, e = tid & 63;     // 8 groups x 16 blocks
        float sacc = 0.0f;
        for (int b = qq * 16; b < qq * 16 + 16; b++) sacc += g_part_load[b * E + e];
        redsm[tid] = sacc;
        __syncthreads();
        if (tid < E) {
            float S = 0.0f;
            #pragma unroll
            for (int q2 = 0; q2 < 8; q2++) S += redsm[q2 * 64 + tid];
            float d = S * (1.0f / (float)NTOK) - (1.0f / (float)E);
            redsm[tid] = d * d;
        }
        __syncthreads();
        if (tid < 32) {
            float v = redsm[tid] + redsm[tid + 32];
            #pragma unroll
            for (int o = 16; o > 0; o >>= 1) v += __shfl_down_sync(0xFFFFFFFFu, v, o);
            if (tid == 0) redsm[0] = v;    // lb sum
        }
        if (tid >= 128 && tid < 256) {
            float zv = g_part_z[tid - 128];
            #pragma unroll
            for (int o = 16; o > 0; o >>= 1) zv += __shfl_down_sync(0xFFFFFFFFu, zv, o);
            if (((tid - 128) & 31) == 0) zred2[(tid - 128) >> 5] = zv;
        }
        __syncthreads();
        if (tid == 0) {
            float z = zred2[0] + zred2[1] + zred2[2] + zred2[3];
            float total = 0.01f * redsm[0] + 1e-4f * (z / (float)NTOK);
            if (out_size > 4 * NTOK) out[4 * NTOK] = total;
            g_arrive = 0;
        }
    }
}

extern "C" void kernel_launch(void* const* d_in, const int* in_sizes, int n_in,
                              void* d_out, int out_size)
{
    const float* x = (const float*)d_in[0];
    const float* W = (const float*)d_in[1];
    float* out = (float*)d_out;

    cudaFuncSetAttribute(gate_kernel, cudaFuncAttributeMaxDynamicSharedMemorySize, SMEM_DYN);
    prep_kernel<<<E, 256>>>(W);
    gate_kernel<<<NBLK, 512, SMEM_DYN>>>(x, out, out_size);
}